// round 8
// baseline (speedup 1.0000x reference)
#include <cuda_runtime.h>
#include <cuda_fp16.h>
#include <mma.h>

using namespace nvcuda;

#define MAX_NODES 100000
#define HID 128
#define KEXT 144          // 128 Z dims + 1 bias row + 15 zero pad
#define LDA2 152          // smem row stride (halves)
#define YT 222            // persistent grid.y: 2*222 = 444 CTAs = 148 SM * 3
#define TILES 1563        // ceil(100000 / 64)

// Precomputed per-node projections, fp16 (51.2 MB total -> L2-resident)
// g_U = Z @ W1[0:128,:] + b1 (bias folded via K-extension row)
__device__ __half g_U[(size_t)MAX_NODES * HID];
__device__ __half g_V[(size_t)MAX_NODES * HID];   // Z @ W1[128:256,:]

extern __shared__ char smem_raw[];

// ---------------------------------------------------------------------------
// Persistent precompute: grid (2, YT). blockIdx.x = chunk (0 -> U+b1, 1 -> V).
// Each CTA: stage B once (fp32 W1 -> fp16 smem, bias row, zero rows), then
// loop tiles with stride YT. Per tile: prefetch NEXT A tile into registers
// before the MMA phase (overlaps DRAM latency with HMMA), MMA 9 k-steps,
// epilogue = f32 acc -> f16 fragment -> store_matrix_sync direct to global,
// then STS the prefetched A after the post-MMA sync.
// ---------------------------------------------------------------------------
__global__ void __launch_bounds__(256)
precompute_kernel(const float* __restrict__ z,
                  const float* __restrict__ W1,
                  const float* __restrict__ b1,
                  int n_nodes)
{
    __half* sA = (__half*)smem_raw;              // [64][LDA2]
    __half* sB = sA + 64 * LDA2;                 // [KEXT][LDA2]

    const int tid   = threadIdx.x;
    const int chunk = blockIdx.x;

    // ---- one-time B stage: fp32 W1 rows -> fp16 ----
    const float* Wb = W1 + (size_t)chunk * 128 * HID;
    for (int idx = tid; idx < 128 * 32; idx += 256) {
        int r  = idx >> 5;
        int c4 = (idx & 31) << 2;
        float4 f = *(const float4*)(Wb + (size_t)r * HID + c4);
        __half2 h[2];
        h[0] = __floats2half2_rn(f.x, f.y);
        h[1] = __floats2half2_rn(f.z, f.w);
        *(uint2*)(sB + r * LDA2 + c4) = *(uint2*)h;
    }
    // rows 128..143: row 128 = b1 (chunk 0) else zeros
    for (int idx = tid; idx < 16 * 32; idx += 256) {
        int r  = 128 + (idx >> 5);
        int c4 = (idx & 31) << 2;
        __half2 h[2];
        if (r == 128 && chunk == 0) {
            float4 f = *(const float4*)(b1 + c4);
            h[0] = __floats2half2_rn(f.x, f.y);
            h[1] = __floats2half2_rn(f.z, f.w);
        } else {
            h[0] = h[1] = __floats2half2_rn(0.f, 0.f);
        }
        *(uint2*)(sB + r * LDA2 + c4) = *(uint2*)h;
    }
    // A constant cols 128..143 (col 128 = 1.0 bias multiplier; rest 0).
    // Written once; tile staging only touches cols 0..127.
    for (int i = tid; i < 64 * 4; i += 256) {
        int r  = i >> 2;
        int c4 = 128 + (i & 3) * 4;
        __half h4[4];
        h4[0] = __float2half((c4 == 128) ? 1.0f : 0.0f);
        h4[1] = __float2half(0.0f);
        h4[2] = __float2half(0.0f);
        h4[3] = __float2half(0.0f);
        *(uint2*)(sA + r * LDA2 + c4) = *(uint2*)h4;
    }

    // ---- stage A for this CTA's first tile ----
    int tile = blockIdx.y;
    {
        const int m0   = tile * 64;
        const int mrem = n_nodes - m0;
        for (int idx = tid; idx < 64 * 32; idx += 256) {
            int r  = idx >> 5;
            int c4 = (idx & 31) << 2;
            __half2 h[2];
            if (r < mrem) {
                float4 f = *(const float4*)(z + (size_t)(m0 + r) * HID + c4);
                h[0] = __floats2half2_rn(f.x, f.y);
                h[1] = __floats2half2_rn(f.z, f.w);
            } else {
                h[0] = h[1] = __floats2half2_rn(0.f, 0.f);
            }
            *(uint2*)(sA + r * LDA2 + c4) = *(uint2*)h;
        }
    }

    const int warpId = tid >> 5;
    const int wm = (warpId & 3) * 16;
    const int wn = (warpId >> 2) * 64;
    __half* outb = (chunk == 0) ? g_U : g_V;

    while (tile < TILES) {
        const int  next      = tile + YT;
        const bool have_next = (next < TILES);

        __syncthreads();                         // sA(tile) + sB visible

        // Prefetch next A tile into registers (overlaps with MMA below)
        float4 pf[8];
        {
            const int nm0   = next * 64;
            const int nmrem = n_nodes - nm0;
            #pragma unroll
            for (int i = 0; i < 8; i++) {
                int idx = tid + i * 256;
                int r   = idx >> 5;
                int c4  = (idx & 31) << 2;
                if (have_next && r < nmrem)
                    pf[i] = *(const float4*)(z + (size_t)(nm0 + r) * HID + c4);
                else
                    pf[i] = make_float4(0.f, 0.f, 0.f, 0.f);
            }
        }

        // MMA + direct epilogue for current tile
        const int m0 = tile * 64;
        if (m0 + wm < n_nodes) {                 // n_nodes % 16 == 0
            wmma::fragment<wmma::accumulator, 16, 16, 16, float> acc[4];
            #pragma unroll
            for (int j = 0; j < 4; j++) wmma::fill_fragment(acc[j], 0.0f);

            #pragma unroll
            for (int k0 = 0; k0 < KEXT; k0 += 16) {
                wmma::fragment<wmma::matrix_a, 16, 16, 16, __half, wmma::row_major> a;
                wmma::load_matrix_sync(a, sA + wm * LDA2 + k0, LDA2);
                #pragma unroll
                for (int j = 0; j < 4; j++) {
                    wmma::fragment<wmma::matrix_b, 16, 16, 16, __half, wmma::row_major> b;
                    wmma::load_matrix_sync(b, sB + k0 * LDA2 + wn + j * 16, LDA2);
                    wmma::mma_sync(acc[j], a, b, acc[j]);
                }
            }

            #pragma unroll
            for (int j = 0; j < 4; j++) {
                wmma::fragment<wmma::accumulator, 16, 16, 16, __half> hacc;
                #pragma unroll
                for (int i = 0; i < hacc.num_elements; i++)
                    hacc.x[i] = __float2half(acc[j].x[i]);
                wmma::store_matrix_sync(outb + (size_t)(m0 + wm) * HID + wn + j * 16,
                                        hacc, HID, wmma::mem_row_major);
            }
        }

        __syncthreads();                         // MMA done reading sA

        if (have_next) {
            #pragma unroll
            for (int i = 0; i < 8; i++) {
                int idx = tid + i * 256;
                int r   = idx >> 5;
                int c4  = (idx & 31) << 2;
                __half2 h[2];
                h[0] = __floats2half2_rn(pf[i].x, pf[i].y);
                h[1] = __floats2half2_rn(pf[i].z, pf[i].w);
                *(uint2*)(sA + r * LDA2 + c4) = *(uint2*)h;
            }
        }
        tile = next;
    }
}

// ---------------------------------------------------------------------------
// Edge kernel (unchanged): 16 lanes per edge-slot, 2 slots per warp, 2 edges
// per slot per iter. b1 pre-folded into U: hadd2+hmax2+hfma2, half2 dot,
// fp32 shfl reduce, sigmoid.
// ---------------------------------------------------------------------------
__global__ void __launch_bounds__(256)
edge_kernel(const int* __restrict__ ei,
            const float* __restrict__ W2,
            const float* __restrict__ b2,
            float* __restrict__ out,
            int E)
{
    const int lane = threadIdx.x & 31;
    const int sub  = lane >> 4;
    const int l16  = lane & 15;
    const int gw   = (blockIdx.x * blockDim.x + threadIdx.x) >> 5;
    const int nw   = (gridDim.x * blockDim.x) >> 5;

    __half2 w2h[4];
    {
        const float* w2p = W2 + l16 * 8;
        #pragma unroll
        for (int j = 0; j < 4; j++)
            w2h[j] = __floats2half2_rn(w2p[2 * j], w2p[2 * j + 1]);
    }
    const float   b2v   = __ldg(b2);
    const __half2 zero2 = __floats2half2_rn(0.f, 0.f);

    const __half* Ub = g_U + l16 * 8;
    const __half* Vb = g_V + l16 * 8;

    for (int e4 = gw * 4; e4 < E; e4 += nw * 4) {
        const int  eA = e4 + sub * 2;
        const int  eB = eA + 1;
        const bool vA = (eA < E);
        const bool vB = (eB < E);

        int s0 = vA ? __ldg(ei + eA)     : 0;
        int d0 = vA ? __ldg(ei + E + eA) : 0;
        int s1 = vB ? __ldg(ei + eB)     : 0;
        int d1 = vB ? __ldg(ei + E + eB) : 0;

        uint4 u0 = *(const uint4*)(Ub + (size_t)s0 * HID);
        uint4 v0 = *(const uint4*)(Vb + (size_t)d0 * HID);
        uint4 u1 = *(const uint4*)(Ub + (size_t)s1 * HID);
        uint4 v1 = *(const uint4*)(Vb + (size_t)d1 * HID);

        const __half2* u0h = (const __half2*)&u0;
        const __half2* v0h = (const __half2*)&v0;
        const __half2* u1h = (const __half2*)&u1;
        const __half2* v1h = (const __half2*)&v1;

        __half2 p0 = zero2, p1 = zero2;
        #pragma unroll
        for (int j = 0; j < 4; j++) {
            __half2 t0 = __hmax2(__hadd2(u0h[j], v0h[j]), zero2);
            __half2 t1 = __hmax2(__hadd2(u1h[j], v1h[j]), zero2);
            p0 = __hfma2(t0, w2h[j], p0);
            p1 = __hfma2(t1, w2h[j], p1);
        }

        float a0 = __low2float(p0) + __high2float(p0);
        float a1 = __low2float(p1) + __high2float(p1);

        #pragma unroll
        for (int o = 8; o; o >>= 1) {
            a0 += __shfl_xor_sync(0xffffffffu, a0, o);
            a1 += __shfl_xor_sync(0xffffffffu, a1, o);
        }

        if (l16 == 0) {
            if (vA) out[eA] = 1.0f / (1.0f + __expf(-(a0 + b2v)));
            if (vB) out[eB] = 1.0f / (1.0f + __expf(-(a1 + b2v)));
        }
    }
}

// ---------------------------------------------------------------------------
// inputs: z f32[100000*128], edge_index i32[2*1000000],
//         W1 f32[256*128], b1 f32[128], W2 f32[128], b2 f32[1]
// output: f32[1000000]
// ---------------------------------------------------------------------------
extern "C" void kernel_launch(void* const* d_in, const int* in_sizes, int n_in,
                              void* d_out, int out_size)
{
    (void)n_in; (void)out_size;
    const float* z  = (const float*)d_in[0];
    const int*   ei = (const int*)  d_in[1];
    const float* W1 = (const float*)d_in[2];
    const float* b1 = (const float*)d_in[3];
    const float* W2 = (const float*)d_in[4];
    const float* b2 = (const float*)d_in[5];

    const int n_nodes = in_sizes[0] / HID;
    const int E       = in_sizes[1] / 2;

    const int smem_bytes = (64 + KEXT) * LDA2 * sizeof(__half);   // 63,232 B
    cudaFuncSetAttribute(precompute_kernel,
                         cudaFuncAttributeMaxDynamicSharedMemorySize, smem_bytes);

    dim3 pgrid(2, YT);
    precompute_kernel<<<pgrid, 256, smem_bytes>>>(z, W1, b1, n_nodes);

    edge_kernel<<<4440, 256>>>(ei, W2, b2, (float*)d_out, E);
}

// round 11
// speedup vs baseline: 1.2292x; 1.2292x over previous
#include <cuda_runtime.h>
#include <cuda_fp16.h>
#include <mma.h>

using namespace nvcuda;

#define MAX_NODES 100000
#define HID   128
#define KEXT  144         // 128 Z dims + 1 bias row + 15 zero pad
#define LDA2  152         // sA row stride (halves): conflict-free ldmatrix
#define LDB2  264         // sB row stride (halves): 256 + 8 pad
#define NTILES 1563       // ceil(100000 / 64)
#define PGRID  296        // persistent CTAs = 148 SMs * 2

// Per-node projections, fp16 (51.2 MB total -> L2-resident).
// g_U = Z @ W1[0:128,:] + b1 (bias folded via K-extension row); g_V = Z @ W1[128:256,:].
__device__ __half g_U[(size_t)MAX_NODES * HID];
__device__ __half g_V[(size_t)MAX_NODES * HID];

extern __shared__ char smem_raw[];

// ---------------------------------------------------------------------------
// Persistent fused precompute (single GEMM over combined 256-wide N).
// Each of 296 CTAs stages the full combined B (144x256 fp16: U half, V half,
// bias row) ONCE, then strides over m-tiles. Per tile: stage A (Z->fp16,
// 64 rows), 9 k-step HMMA into a 64x256 output (8 warps, 16x128 each),
// epilogue f32 acc -> f16 fragment -> store_matrix_sync direct to g_U/g_V.
// Z DRAM-read exactly once (the split-chunk R7 version read it twice).
// ---------------------------------------------------------------------------
__global__ void __launch_bounds__(256)
lp_precompute(const float* __restrict__ z,
              const float* __restrict__ W1,
              const float* __restrict__ b1,
              int n_nodes)
{
    __half* sA = (__half*)smem_raw;              // [64][LDA2]
    __half* sB = sA + 64 * LDA2;                 // [KEXT][LDB2]

    const int tid = threadIdx.x;

    // One-time B stage: combined [k][n]; n<128 -> W1[k][n], n>=128 -> W1[128+k][n-128]
    for (int idx = tid; idx < 128 * 64; idx += 256) {
        const int r  = idx >> 6;
        const int c4 = (idx & 63) << 2;
        const float* src = (c4 < 128)
            ? (W1 + (size_t)r * HID + c4)
            : (W1 + (size_t)(128 + r) * HID + (c4 - 128));
        const float4 f = *(const float4*)src;
        __half2 h[2];
        h[0] = __floats2half2_rn(f.x, f.y);
        h[1] = __floats2half2_rn(f.z, f.w);
        *(uint2*)(sB + r * LDB2 + c4) = *(uint2*)h;
    }
    // B rows 128..143: row 128 = [b1 | 0], remainder zero
    for (int idx = tid; idx < 16 * 64; idx += 256) {
        const int r  = 128 + (idx >> 6);
        const int c4 = (idx & 63) << 2;
        __half2 h[2];
        if (r == 128 && c4 < 128) {
            const float4 f = *(const float4*)(b1 + c4);
            h[0] = __floats2half2_rn(f.x, f.y);
            h[1] = __floats2half2_rn(f.z, f.w);
        } else {
            h[0] = h[1] = __floats2half2_rn(0.f, 0.f);
        }
        *(uint2*)(sB + r * LDB2 + c4) = *(uint2*)h;
    }
    // A constant cols 128..143: col 128 = 1.0 (bias multiplier), rest 0; set once
    for (int i = tid; i < 64 * 4; i += 256) {
        const int r  = i >> 2;
        const int c4 = 128 + (i & 3) * 4;
        __half h4[4];
        h4[0] = __float2half((c4 == 128) ? 1.0f : 0.0f);
        h4[1] = __float2half(0.0f);
        h4[2] = __float2half(0.0f);
        h4[3] = __float2half(0.0f);
        *(uint2*)(sA + r * LDA2 + c4) = *(uint2*)h4;
    }

    const int warpId = tid >> 5;
    const int wm = (warpId & 3) * 16;            // warp m offset within tile
    const int nh = warpId >> 2;                  // 0 -> U half, 1 -> V half
    const int ncol = nh * 128;                   // sB column base for this warp
    __half* const outb = (nh == 0) ? g_U : g_V;

    #pragma unroll 1
    for (int tile = blockIdx.x; tile < NTILES; tile += PGRID) {
        const int m0   = tile * 64;
        const int mrem = n_nodes - m0;

        __syncthreads();   // prior MMA done reading sA (and sB ready on t=0)

        // Stage A cols 0..127: Z fp32 -> fp16, zero-pad past-end rows
        for (int idx = tid; idx < 64 * 32; idx += 256) {
            const int r  = idx >> 5;
            const int c4 = (idx & 31) << 2;
            __half2 h[2];
            if (r < mrem) {
                const float4 f = *(const float4*)(z + (size_t)(m0 + r) * HID + c4);
                h[0] = __floats2half2_rn(f.x, f.y);
                h[1] = __floats2half2_rn(f.z, f.w);
            } else {
                h[0] = h[1] = __floats2half2_rn(0.f, 0.f);
            }
            *(uint2*)(sA + r * LDA2 + c4) = *(uint2*)h;
        }
        __syncthreads();

        if (m0 + wm < n_nodes) {                 // n_nodes % 16 == 0
            wmma::fragment<wmma::accumulator, 16, 16, 16, float> acc[8];
            #pragma unroll
            for (int j = 0; j < 8; j++) wmma::fill_fragment(acc[j], 0.0f);

            #pragma unroll
            for (int k0 = 0; k0 < KEXT; k0 += 16) {
                wmma::fragment<wmma::matrix_a, 16, 16, 16, __half, wmma::row_major> a;
                wmma::load_matrix_sync(a, sA + wm * LDA2 + k0, LDA2);
                #pragma unroll
                for (int j = 0; j < 8; j++) {
                    wmma::fragment<wmma::matrix_b, 16, 16, 16, __half, wmma::row_major> b;
                    wmma::load_matrix_sync(b, sB + k0 * LDB2 + ncol + j * 16, LDB2);
                    wmma::mma_sync(acc[j], a, b, acc[j]);
                }
            }

            #pragma unroll
            for (int j = 0; j < 8; j++) {
                wmma::fragment<wmma::accumulator, 16, 16, 16, __half> hacc;
                #pragma unroll
                for (int i = 0; i < hacc.num_elements; i++)
                    hacc.x[i] = __float2half(acc[j].x[i]);
                wmma::store_matrix_sync(outb + (size_t)(m0 + wm) * HID + j * 16,
                                        hacc, HID, wmma::mem_row_major);
            }
        }
    }
}

// ---------------------------------------------------------------------------
// Edge kernel (unchanged since R6): 16 lanes per edge-slot, 2 slots per warp,
// 2 edges per slot per iteration. b1 pre-folded into U: hadd2+hmax2+hfma2,
// half2 dot, fp32 shfl-pair reduce, sigmoid.
// ---------------------------------------------------------------------------
__global__ void __launch_bounds__(256)
lp_edge(const int* __restrict__ ei,
        const float* __restrict__ W2,
        const float* __restrict__ b2,
        float* __restrict__ out,
        int E)
{
    const int lane = threadIdx.x & 31;
    const int sub  = lane >> 4;
    const int l16  = lane & 15;
    const int gw   = (blockIdx.x * blockDim.x + threadIdx.x) >> 5;
    const int nw   = (gridDim.x * blockDim.x) >> 5;

    __half2 w2h[4];
    {
        const float* w2p = W2 + l16 * 8;
        #pragma unroll
        for (int j = 0; j < 4; j++)
            w2h[j] = __floats2half2_rn(w2p[2 * j], w2p[2 * j + 1]);
    }
    const float   b2v   = __ldg(b2);
    const __half2 zero2 = __floats2half2_rn(0.f, 0.f);

    const __half* Ub = g_U + l16 * 8;
    const __half* Vb = g_V + l16 * 8;

    for (int e4 = gw * 4; e4 < E; e4 += nw * 4) {
        const int  eA = e4 + sub * 2;
        const int  eB = eA + 1;
        const bool vA = (eA < E);
        const bool vB = (eB < E);

        const int s0 = vA ? __ldg(ei + eA)     : 0;
        const int d0 = vA ? __ldg(ei + E + eA) : 0;
        const int s1 = vB ? __ldg(ei + eB)     : 0;
        const int d1 = vB ? __ldg(ei + E + eB) : 0;

        const uint4 u0 = *(const uint4*)(Ub + (size_t)s0 * HID);
        const uint4 v0 = *(const uint4*)(Vb + (size_t)d0 * HID);
        const uint4 u1 = *(const uint4*)(Ub + (size_t)s1 * HID);
        const uint4 v1 = *(const uint4*)(Vb + (size_t)d1 * HID);

        const __half2* u0h = (const __half2*)&u0;
        const __half2* v0h = (const __half2*)&v0;
        const __half2* u1h = (const __half2*)&u1;
        const __half2* v1h = (const __half2*)&v1;

        __half2 p0 = zero2, p1 = zero2;
        #pragma unroll
        for (int j = 0; j < 4; j++) {
            const __half2 t0 = __hmax2(__hadd2(u0h[j], v0h[j]), zero2);
            const __half2 t1 = __hmax2(__hadd2(u1h[j], v1h[j]), zero2);
            p0 = __hfma2(t0, w2h[j], p0);
            p1 = __hfma2(t1, w2h[j], p1);
        }

        float a0 = __low2float(p0) + __high2float(p0);
        float a1 = __low2float(p1) + __high2float(p1);

        #pragma unroll
        for (int o = 8; o; o >>= 1) {
            a0 += __shfl_xor_sync(0xffffffffu, a0, o);
            a1 += __shfl_xor_sync(0xffffffffu, a1, o);
        }

        if (l16 == 0) {
            if (vA) out[eA] = 1.0f / (1.0f + __expf(-(a0 + b2v)));
            if (vB) out[eB] = 1.0f / (1.0f + __expf(-(a1 + b2v)));
        }
    }
}

// ---------------------------------------------------------------------------
// inputs: z f32[100000*128], edge_index i32[2*1000000],
//         W1 f32[256*128], b1 f32[128], W2 f32[128], b2 f32[1]
// output: f32[1000000]
// ---------------------------------------------------------------------------
extern "C" void kernel_launch(void* const* d_in, const int* in_sizes, int n_in,
                              void* d_out, int out_size)
{
    (void)n_in; (void)out_size;
    const float* z  = (const float*)d_in[0];
    const int*   ei = (const int*)  d_in[1];
    const float* W1 = (const float*)d_in[2];
    const float* b1 = (const float*)d_in[3];
    const float* W2 = (const float*)d_in[4];
    const float* b2 = (const float*)d_in[5];

    const int n_nodes = in_sizes[0] / HID;
    const int E       = in_sizes[1] / 2;

    const int smem_bytes = (64 * LDA2 + KEXT * LDB2) * (int)sizeof(__half);  // 95,488 B
    cudaFuncSetAttribute(lp_precompute,
                         cudaFuncAttributeMaxDynamicSharedMemorySize, smem_bytes);

    lp_precompute<<<PGRID, 256, smem_bytes>>>(z, W1, b1, n_nodes);

    lp_edge<<<4440, 256>>>(ei, W2, b2, (float*)d_out, E);
}